// round 3
// baseline (speedup 1.0000x reference)
#include <cuda_runtime.h>

#define NUM_CLS   8
#define MAX_INST  64
#define NB        32            // batch
#define HW        (1024*1024)   // pixels per sample
#define HTHREADS  128
#define CHUNKS    32            // blocks per sample along pixel dim

__device__ int g_inst_sizes[NB * MAX_INST];

// ---------------- kernel 0: zero the accumulator ----------------
__global__ void zero_kernel() {
    int i = blockIdx.x * blockDim.x + threadIdx.x;
    if (i < NB * MAX_INST) g_inst_sizes[i] = 0;
}

// ---------------- kernel 1: per-sample 64-bin histogram ----------------
// Privatized per-thread counters in shared: cnt[bin*HTHREADS + tid].
// bank = tid % 32 -> conflict-free LDS/STS regardless of bin value.
__global__ __launch_bounds__(HTHREADS) void hist_kernel(const int* __restrict__ mask) {
    __shared__ unsigned int cnt[MAX_INST * HTHREADS];   // 32 KB

    const int tid = threadIdx.x;

    #pragma unroll
    for (int i = tid; i < MAX_INST * HTHREADS; i += HTHREADS) cnt[i] = 0u;
    __syncthreads();

    const int sample = blockIdx.y;
    const int chunk  = blockIdx.x;
    const int elems_per_block = HW / CHUNKS;        // 32768
    const int vecs_per_block  = elems_per_block / 4; // 8192 int4 loads

    const int4* __restrict__ base =
        (const int4*)(mask + (size_t)sample * HW + (size_t)chunk * elems_per_block);

    #pragma unroll 4
    for (int i = tid; i < vecs_per_block; i += HTHREADS) {
        int4 v = base[i];
        cnt[(v.x & 63) * HTHREADS + tid]++;
        cnt[(v.y & 63) * HTHREADS + tid]++;
        cnt[(v.z & 63) * HTHREADS + tid]++;
        cnt[(v.w & 63) * HTHREADS + tid]++;
    }
    __syncthreads();

    // Reduce 128 private counters per bin; staggered index -> conflict-free.
    if (tid < MAX_INST) {
        unsigned int s = 0;
        #pragma unroll 8
        for (int j = 0; j < HTHREADS; j++)
            s += cnt[tid * HTHREADS + ((tid + j) & (HTHREADS - 1))];
        atomicAdd(&g_inst_sizes[sample * MAX_INST + tid], (int)s);
    }
}

// ---------------- kernel 2: gather/scatter + BCE loss ----------------
__global__ __launch_bounds__(256) void loss_kernel(const float* __restrict__ pred,
                                                   const int*   __restrict__ label_raw,
                                                   float* __restrict__ out) {
    __shared__ int   isz[NB * MAX_INST];
    __shared__ int   cnts[NB * NUM_CLS];
    __shared__ float red[8];
    __shared__ int   s_is64;

    const int tid = threadIdx.x;

    for (int i = tid; i < NB * MAX_INST; i += 256) isz[i] = g_inst_sizes[i];
    if (tid < NB * NUM_CLS) cnts[tid] = 0;

    // Detect int64 vs int32 layout of label_gt: values are < 32, so for a
    // little-endian int64 array every odd 32-bit word (high half) is 0.
    if (tid == 0) {
        int all_zero = 1;
        for (int j = 0; j < 64; j++)
            if (label_raw[2 * j + 1] != 0) { all_zero = 0; break; }
        s_is64 = all_zero;
    }
    __syncthreads();

    const int is64 = s_is64;
    // pairs p = b*64 + k, total 2048
    for (int p = tid; p < NB * 64; p += 256) {
        int b = p >> 6;
        int id, lbl;
        if (is64) { id = label_raw[4 * p];     lbl = label_raw[4 * p + 2]; }
        else      { id = label_raw[2 * p];     lbl = label_raw[2 * p + 1]; }
        if (lbl > 0 && lbl <= NUM_CLS)
            atomicAdd(&cnts[b * NUM_CLS + lbl - 1], isz[b * MAX_INST + (id & (MAX_INST - 1))]);
    }
    __syncthreads();

    float term = 0.0f;
    if (tid < NB * NUM_CLS) {
        float x  = pred[tid];
        float cl = fminf((float)cnts[tid] * (1.0f / 100.0f), 1.0f);
        term = fmaxf(x, 0.0f) - x * cl + log1pf(expf(-fabsf(x)));
    }
    // block reduce (256 -> 1)
    #pragma unroll
    for (int o = 16; o; o >>= 1) term += __shfl_down_sync(0xffffffffu, term, o);
    if ((tid & 31) == 0) red[tid >> 5] = term;
    __syncthreads();
    if (tid < 8) {
        float s = red[tid];
        #pragma unroll
        for (int o = 4; o; o >>= 1) s += __shfl_down_sync(0xffu, s, o);
        if (tid == 0) out[0] = s * (1.0f / (float)(NB * NUM_CLS));
    }
}

// ---------------- launch ----------------
extern "C" void kernel_launch(void* const* d_in, const int* in_sizes, int n_in,
                              void* d_out, int out_size) {
    const float* pred  = (const float*)d_in[0];          // [32, 8] f32
    const int*   mask  = (const int*)d_in[1];            // [32, 1024, 1024] i32
    const int*   label = (const int*)d_in[2];            // [32, 64, 2] i32 or i64
    float*       out   = (float*)d_out;

    zero_kernel<<<8, 256>>>();
    dim3 grid(CHUNKS, NB);
    hist_kernel<<<grid, HTHREADS>>>(mask);
    loss_kernel<<<1, 256>>>(pred, label, out);
}

// round 4
// speedup vs baseline: 1.2249x; 1.2249x over previous
#include <cuda_runtime.h>

#define NUM_CLS   8
#define MAX_INST  64
#define NB        32            // batch
#define HW        (1024*1024)   // pixels per sample
#define HT        256           // threads per hist block
#define CHUNKS    32            // blocks per sample along pixel dim

// Per-block histogram partials, written with plain stores (no zeroing needed).
__device__ int g_part[NB * CHUNKS * MAX_INST];   // 256 KB

// ---------------- kernel 1: per-sample 64-bin histogram ----------------
// Privatized per-thread u16 counters: cnt[bin*HT + tid]. bank = f(tid) ->
// conflict-free LDS/STS regardless of bin. Max 128 elems/thread -> no overflow.
__global__ __launch_bounds__(HT) void hist_kernel(const int* __restrict__ mask) {
    __shared__ unsigned short cnt[MAX_INST * HT];   // 32 KB
    __shared__ unsigned int   psum[HT];

    const int tid = threadIdx.x;
    unsigned int* cnt32 = (unsigned int*)cnt;

    #pragma unroll
    for (int i = tid; i < MAX_INST * HT / 2; i += HT) cnt32[i] = 0u;
    __syncthreads();

    const int sample = blockIdx.y;
    const int chunk  = blockIdx.x;
    const int elems  = HW / CHUNKS;     // 32768 per block
    const int vecs   = elems / 4;       // 8192 int4

    const int4* __restrict__ p =
        (const int4*)(mask + (size_t)sample * HW + (size_t)chunk * elems) + tid;

#define INC(v) cnt[((v) & 63) * HT + tid]++

    // 8192 int4 / 256 thr = 32 int4/thread = 8 iters of 4 explicitly-batched loads
    #pragma unroll 2
    for (int it = 0; it < vecs / (HT * 4); it++) {
        int4 a = p[0 * HT];
        int4 b = p[1 * HT];
        int4 c = p[2 * HT];
        int4 d = p[3 * HT];
        p += 4 * HT;
        INC(a.x); INC(a.y); INC(a.z); INC(a.w);
        INC(b.x); INC(b.y); INC(b.z); INC(b.w);
        INC(c.x); INC(c.y); INC(c.z); INC(c.w);
        INC(d.x); INC(d.y); INC(d.z); INC(d.w);
    }
#undef INC
    __syncthreads();

    // Reduce 256 u16 lanes per bin. 4 threads per bin (j = tid>>6), each sums
    // 32 packed words with a tid-stagger -> conflict-free LDS.
    {
        const int b = tid & 63;
        const int j = tid >> 6;
        unsigned int s = 0;
        #pragma unroll
        for (int i = 0; i < 32; i++) {
            unsigned int w = cnt32[b * (HT / 2) + j * 32 + ((i + tid) & 31)];
            s += (w & 0xffffu) + (w >> 16);
        }
        psum[tid] = s;
    }
    __syncthreads();
    if (tid < MAX_INST) {
        unsigned int t = psum[tid] + psum[tid + 64] + psum[tid + 128] + psum[tid + 192];
        g_part[(sample * CHUNKS + chunk) * MAX_INST + tid] = (int)t;
    }
}

// ---------------- kernel 2: partial-sum + gather/scatter + BCE loss ----------------
__global__ __launch_bounds__(256) void loss_kernel(const float* __restrict__ pred,
                                                   const int*   __restrict__ label_raw,
                                                   float* __restrict__ out) {
    __shared__ int   isz[NB * MAX_INST];
    __shared__ int   cnts[NB * NUM_CLS];
    __shared__ float red[8];
    __shared__ int   s_is64;

    const int tid = threadIdx.x;

    // Sum histogram partials over chunks (L2-resident, 256 KB total).
    for (int p0 = tid; p0 < NB * MAX_INST; p0 += 256) {
        int s = p0 >> 6, b = p0 & 63;
        int acc = 0;
        #pragma unroll
        for (int c = 0; c < CHUNKS; c++)
            acc += g_part[(s * CHUNKS + c) * MAX_INST + b];
        isz[p0] = acc;
    }
    if (tid < NB * NUM_CLS) cnts[tid] = 0;

    // Detect int64 vs int32 layout of label_gt: values < 32, so for a
    // little-endian int64 array every odd 32-bit word (high half) is 0.
    if (tid == 0) {
        int all_zero = 1;
        for (int j = 0; j < 64; j++)
            if (label_raw[2 * j + 1] != 0) { all_zero = 0; break; }
        s_is64 = all_zero;
    }
    __syncthreads();

    const int is64 = s_is64;
    for (int p = tid; p < NB * 64; p += 256) {
        int b = p >> 6;
        int id, lbl;
        if (is64) { id = label_raw[4 * p]; lbl = label_raw[4 * p + 2]; }
        else      { id = label_raw[2 * p]; lbl = label_raw[2 * p + 1]; }
        if (lbl > 0 && lbl <= NUM_CLS)
            atomicAdd(&cnts[b * NUM_CLS + lbl - 1], isz[b * MAX_INST + (id & (MAX_INST - 1))]);
    }
    __syncthreads();

    float term = 0.0f;
    if (tid < NB * NUM_CLS) {
        float x  = pred[tid];
        float cl = fminf((float)cnts[tid] * (1.0f / 100.0f), 1.0f);
        term = fmaxf(x, 0.0f) - x * cl + log1pf(expf(-fabsf(x)));
    }
    #pragma unroll
    for (int o = 16; o; o >>= 1) term += __shfl_down_sync(0xffffffffu, term, o);
    if ((tid & 31) == 0) red[tid >> 5] = term;
    __syncthreads();
    if (tid < 8) {
        float s = red[tid];
        #pragma unroll
        for (int o = 4; o; o >>= 1) s += __shfl_down_sync(0xffu, s, o);
        if (tid == 0) out[0] = s * (1.0f / (float)(NB * NUM_CLS));
    }
}

// ---------------- launch ----------------
extern "C" void kernel_launch(void* const* d_in, const int* in_sizes, int n_in,
                              void* d_out, int out_size) {
    const float* pred  = (const float*)d_in[0];          // [32, 8] f32
    const int*   mask  = (const int*)d_in[1];            // [32, 1024, 1024] i32
    const int*   label = (const int*)d_in[2];            // [32, 64, 2] i32 or i64
    float*       out   = (float*)d_out;

    dim3 grid(CHUNKS, NB);
    hist_kernel<<<grid, HT>>>(mask);
    loss_kernel<<<1, 256>>>(pred, label, out);
}